// round 13
// baseline (speedup 1.0000x reference)
#include <cuda_runtime.h>
#include <cuda_fp16.h>
#include <cstdint>
#include <cstddef>

// Problem constants (fixed by the dataset)
static constexpr int M_TOTAL = 8192;   // B*S = 4*2048
static constexpr int N_TOTAL = 4096;
static constexpr int K_TOTAL = 4096;
static constexpr int GROUPS  = 64;     // K / 64

// GEMM tiling: CTA 128x256, 8 warps as 2(m) x 4(n), warp tile 64x64
static constexpr int BM = 128;
static constexpr int BN = 256;
static constexpr int BK = 64;                 // 64 fp16 = 128B per row
static constexpr int STAGES = 4;
static constexpr int KITERS = K_TOTAL / BK;   // 64
static constexpr int NTHREADS = 256;

static constexpr int A_STAGE_BYTES = BM * BK * 2;   // 16384
static constexpr int B_STAGE_BYTES = BN * BK * 2;   // 32768
static constexpr int STAGE_BYTES   = A_STAGE_BYTES + B_STAGE_BYTES; // 49152
static constexpr int DATA_OFF      = 1024;
static constexpr int SMEM_BYTES    = DATA_OFF + STAGES * STAGE_BYTES; // 197632

// fp16 scratch (device globals: the sanctioned scratch path)
__device__ __half g_Ah[(size_t)M_TOTAL * K_TOTAL];   // 64 MB
__device__ __half g_Bh[(size_t)N_TOTAL * K_TOTAL];   // 32 MB

// ---------------------------------------------------------------------------
// PTX helpers (baseline sm_80+ PTX — legal at target sm_103)
// ---------------------------------------------------------------------------
__device__ __forceinline__ uint32_t smem_u32(const void* p) {
    uint32_t a;
    asm("{ .reg .u64 t; cvta.to.shared.u64 t, %1; cvt.u32.u64 %0, t; }"
        : "=r"(a) : "l"(p));
    return a;
}

__device__ __forceinline__ void cp_async16(uint32_t dst, const void* src) {
    asm volatile("cp.async.cg.shared.global [%0], [%1], 16;"
                 :: "r"(dst), "l"(src) : "memory");
}

__device__ __forceinline__ void mbar_init(uint32_t addr, uint32_t count) {
    asm volatile("mbarrier.init.shared.b64 [%0], %1;"
                 :: "r"(addr), "r"(count) : "memory");
}

__device__ __forceinline__ void mbar_wait(uint32_t addr, uint32_t parity) {
    asm volatile(
        "{\n\t"
        ".reg .pred P;\n\t"
        "WL_%=:\n\t"
        "mbarrier.try_wait.parity.acquire.cta.shared::cta.b64 P, [%0], %1, 0x989680;\n\t"
        "@!P bra WL_%=;\n\t"
        "}"
        :: "r"(addr), "r"(parity) : "memory");
}

// Relaxed wait: ONLY for producer waits whose post-wait SMEM accesses are
// all async-proxy (cp.async) — ordered by their own completion mechanism.
__device__ __forceinline__ void mbar_wait_relaxed(uint32_t addr, uint32_t parity) {
    asm volatile(
        "{\n\t"
        ".reg .pred P;\n\t"
        "WL_%=:\n\t"
        "mbarrier.try_wait.parity.relaxed.cta.shared::cta.b64 P, [%0], %1, 0x989680;\n\t"
        "@!P bra WL_%=;\n\t"
        "}"
        :: "r"(addr), "r"(parity) : "memory");
}

__device__ __forceinline__ void mbar_arrive(uint32_t addr) {
    asm volatile("mbarrier.arrive.shared.b64 _, [%0];" :: "r"(addr) : "memory");
}

__device__ __forceinline__ void cp_async_arrive(uint32_t addr) {
    asm volatile("cp.async.mbarrier.arrive.noinc.shared.b64 [%0];"
                 :: "r"(addr) : "memory");
}

__device__ __forceinline__ void ldsm4(uint32_t* r, uint32_t addr) {
    asm volatile("ldmatrix.sync.aligned.m8n8.x4.shared.b16 {%0,%1,%2,%3}, [%4];"
                 : "=r"(r[0]), "=r"(r[1]), "=r"(r[2]), "=r"(r[3]) : "r"(addr));
}

__device__ __forceinline__ void mma16816(float* c, const uint32_t* a,
                                         const uint32_t* b) {
    asm volatile(
        "mma.sync.aligned.m16n8k16.row.col.f32.f16.f16.f32 "
        "{%0,%1,%2,%3}, {%4,%5,%6,%7}, {%8,%9}, {%0,%1,%2,%3};"
        : "+f"(c[0]), "+f"(c[1]), "+f"(c[2]), "+f"(c[3])
        : "r"(a[0]), "r"(a[1]), "r"(a[2]), "r"(a[3]), "r"(b[0]), "r"(b[1]));
}

// ---------------------------------------------------------------------------
// Fused prologue: fp32 x -> fp16 scratch, int2-coded W -> dequantized fp16
// ---------------------------------------------------------------------------
__global__ void prologue_kernel(const float* __restrict__ x,
                                const int* __restrict__ wq,
                                const float* __restrict__ scale,
                                const float* __restrict__ zp) {
    if (blockIdx.x < 16384) {
        size_t i = ((size_t)blockIdx.x * blockDim.x + threadIdx.x) * 8;
        float4 a = *reinterpret_cast<const float4*>(x + i);
        float4 b = *reinterpret_cast<const float4*>(x + i + 4);
        __half2 h0 = __floats2half2_rn(a.x, a.y);
        __half2 h1 = __floats2half2_rn(a.z, a.w);
        __half2 h2 = __floats2half2_rn(b.x, b.y);
        __half2 h3 = __floats2half2_rn(b.z, b.w);
        uint4 p;
        p.x = *reinterpret_cast<uint32_t*>(&h0);
        p.y = *reinterpret_cast<uint32_t*>(&h1);
        p.z = *reinterpret_cast<uint32_t*>(&h2);
        p.w = *reinterpret_cast<uint32_t*>(&h3);
        *reinterpret_cast<uint4*>(g_Ah + i) = p;
    } else {
        uint32_t c = (blockIdx.x - 16384) * blockDim.x + threadIdx.x;
        uint32_t n  = c >> 9;          // 512 chunks per row (K=4096)
        uint32_t kc = c & 511;
        uint32_t g  = kc >> 3;         // 8 chunks per 64-element group
        float s = __ldg(scale + (size_t)n * GROUPS + g);
        float z = __ldg(zp    + (size_t)n * GROUPS + g);
        const int4* qp =
            reinterpret_cast<const int4*>(wq + ((size_t)n << 12) + kc * 8);
        int4 q0 = qp[0];
        int4 q1 = qp[1];
        __half2 h0 = __floats2half2_rn(((float)q0.x - z) * s, ((float)q0.y - z) * s);
        __half2 h1 = __floats2half2_rn(((float)q0.z - z) * s, ((float)q0.w - z) * s);
        __half2 h2 = __floats2half2_rn(((float)q1.x - z) * s, ((float)q1.y - z) * s);
        __half2 h3 = __floats2half2_rn(((float)q1.z - z) * s, ((float)q1.w - z) * s);
        uint4 p;
        p.x = *reinterpret_cast<uint32_t*>(&h0);
        p.y = *reinterpret_cast<uint32_t*>(&h1);
        p.z = *reinterpret_cast<uint32_t*>(&h2);
        p.w = *reinterpret_cast<uint32_t*>(&h3);
        *reinterpret_cast<uint4*>(g_Bh + ((size_t)n << 12) + kc * 8) = p;
    }
}

// ---------------------------------------------------------------------------
// GEMM: out[M,N] = Ah[M,K] * Bh[N,K]^T + bias, fp16 mma.sync, fp32 accum
// 8 warps (2m x 4n), mbarrier ring, continuous cross-kt fragment pipeline.
// kk=3's MMAs are split around the cross-kt wait so a slow FULL wait never
// blocks a full tile of ready MMAs.
// ---------------------------------------------------------------------------
__global__ void __launch_bounds__(NTHREADS, 1)
gemm_w2a16_kernel(const float* __restrict__ bias, float* __restrict__ out) {
    extern __shared__ char smem[];
    const uint32_t sb    = smem_u32(smem);
    const uint32_t FULL  = sb;        // 4 x 8B
    const uint32_t EMPTY = sb + 32;   // 4 x 8B
    const uint32_t DATA  = sb + DATA_OFF;

    const int tid  = threadIdx.x;
    const int lane = tid & 31;
    const int wid  = tid >> 5;
    const int wm   = wid & 1;     // 2 warps over M (64 rows each)
    const int wn   = wid >> 1;    // 4 warps over N (64 cols each)

    const int m0 = blockIdx.y * BM;
    const int n0 = blockIdx.x * BN;

    if (tid == 0) {
        #pragma unroll
        for (int s = 0; s < STAGES; s++) {
            mbar_init(FULL  + 8 * s, NTHREADS);
            mbar_init(EMPTY + 8 * s, NTHREADS);
        }
    }
    __syncthreads();

    // ---- per-thread producer addresses (hoisted; only +k0 varies) ----
    const int prow = tid >> 3, pcc = tid & 7;     // 32 rows per sweep
    const __half* asrc = g_Ah + (size_t)(m0 + prow) * K_TOTAL + pcc * 8;
    const __half* bsrc = g_Bh + (size_t)(n0 + prow) * K_TOTAL + pcc * 8;
    const uint32_t sw  = (uint32_t)((pcc ^ (prow & 7)) << 4);
    const uint32_t dA  = DATA + (uint32_t)prow * 128 + sw;
    const uint32_t dB  = DATA + A_STAGE_BYTES + (uint32_t)prow * 128 + sw;

    float acc[4][8][4];
    #pragma unroll
    for (int mi = 0; mi < 4; mi++)
        #pragma unroll
        for (int ni = 0; ni < 8; ni++)
            #pragma unroll
            for (int v = 0; v < 4; v++) acc[mi][ni][v] = 0.0f;

    // ---- prologue: issue stages 0..2 ----
    #pragma unroll
    for (int it = 0; it < STAGES - 1; it++) {
        const uint32_t st = it * STAGE_BYTES;
        const size_t   k0 = (size_t)it * BK;
        #pragma unroll
        for (int i = 0; i < 4; i++)   // A: 128 rows, 32 per sweep
            cp_async16(dA + st + i * 4096, asrc + (size_t)(i * 32) * K_TOTAL + k0);
        #pragma unroll
        for (int i = 0; i < 8; i++)   // B: 256 rows, 32 per sweep
            cp_async16(dB + st + i * 4096, bsrc + (size_t)(i * 32) * K_TOTAL + k0);
        cp_async_arrive(FULL + 8 * it);
    }

    // ---- per-thread ldmatrix address components ----
    const int quad = lane >> 3, lr = lane & 7;
    const uint32_t aByte = (uint32_t)((wm * 64 + (quad & 1) * 8 + lr) * 128);
    const int      aSel  = quad >> 1;
    const uint32_t bByte = (uint32_t)(A_STAGE_BYTES +
                           (wn * 64 + (quad >> 1) * 8 + lr) * 128);
    const int      bSel  = quad & 1;

    // double-buffered fragments
    uint32_t afr[2][4][4];
    uint32_t bfr[2][8][2];

    auto load_frags = [&](int buf, uint32_t st, int kk) {
        #pragma unroll
        for (int mi = 0; mi < 4; mi++)
            ldsm4(afr[buf][mi], st + aByte + mi * 2048 +
                  (((kk * 2 + aSel) ^ lr) << 4));
        #pragma unroll
        for (int nb = 0; nb < 4; nb++) {
            uint32_t r[4];
            ldsm4(r, st + bByte + nb * 2048 +
                  (((kk * 2 + bSel) ^ lr) << 4));
            bfr[buf][2 * nb][0]     = r[0]; bfr[buf][2 * nb][1]     = r[1];
            bfr[buf][2 * nb + 1][0] = r[2]; bfr[buf][2 * nb + 1][1] = r[3];
        }
    };

    auto mma_half = [&](int buf, int miLo, int miHi) {
        #pragma unroll
        for (int mi = miLo; mi < miHi; mi++)
            #pragma unroll
            for (int ni = 0; ni < 8; ni++)
                mma16816(acc[mi][ni], afr[buf][mi], bfr[buf][ni]);
    };

    // preamble: wait stage 0, load its kk=0 fragments into buffer 0
    mbar_wait(FULL, 0);
    load_frags(0, DATA, 0);

    for (int kt = 0; kt < KITERS; kt++) {
        const int cslot = kt & (STAGES - 1);
        const uint32_t st = DATA + cslot * STAGE_BYTES;

        // ---- kk = 0 ----
        load_frags(1, st, 1);
        mma_half(0, 0, 4);
        {   // producer: issue stage kt+3 (EMPTY wait is relaxed: cp.async only)
            const int it = kt + STAGES - 1;
            if (it < KITERS) {
                const int islot = it & (STAGES - 1);
                if (it >= STAGES)
                    mbar_wait_relaxed(EMPTY + 8 * islot, ((it >> 2) - 1) & 1);
                const uint32_t pst = islot * STAGE_BYTES;
                const size_t   k0  = (size_t)it * BK;
                #pragma unroll
                for (int i = 0; i < 4; i++)
                    cp_async16(dA + pst + i * 4096,
                               asrc + (size_t)(i * 32) * K_TOTAL + k0);
                #pragma unroll
                for (int i = 0; i < 8; i++)
                    cp_async16(dB + pst + i * 4096,
                               bsrc + (size_t)(i * 32) * K_TOTAL + k0);
                cp_async_arrive(FULL + 8 * islot);
            }
        }

        // ---- kk = 1 ----
        load_frags(0, st, 2);
        mma_half(1, 0, 4);

        // ---- kk = 2 ----
        load_frags(1, st, 3);
        mma_half(0, 0, 4);

        // ---- kk = 3: split MMAs around the cross-kt wait ----
        mma_half(1, 0, 2);          // 16 MMAs always ready to issue
        if (kt + 1 < KITERS) {
            const int nslot = (kt + 1) & (STAGES - 1);
            mbar_wait(FULL + 8 * nslot, ((kt + 1) >> 2) & 1);
            load_frags(0, DATA + nslot * STAGE_BYTES, 0);
            mbar_arrive(EMPTY + 8 * cslot);
        }
        mma_half(1, 2, 4);          // cover the prefetch ldsm latency
    }

    // epilogue: bias add + fp32 store (float2 per fragment row)
    const int orow = m0 + wm * 64 + (lane >> 2);
    const int ocol = n0 + wn * 64 + 2 * (lane & 3);
    #pragma unroll
    for (int ni = 0; ni < 8; ni++) {
        const float bx = __ldg(bias + ocol + ni * 8);
        const float by = __ldg(bias + ocol + ni * 8 + 1);
        #pragma unroll
        for (int mi = 0; mi < 4; mi++) {
            float2 v0 = make_float2(acc[mi][ni][0] + bx, acc[mi][ni][1] + by);
            float2 v1 = make_float2(acc[mi][ni][2] + bx, acc[mi][ni][3] + by);
            *reinterpret_cast<float2*>(
                out + (size_t)(orow + mi * 16) * N_TOTAL + ocol + ni * 8) = v0;
            *reinterpret_cast<float2*>(
                out + (size_t)(orow + mi * 16 + 8) * N_TOTAL + ocol + ni * 8) = v1;
        }
    }
}

// ---------------------------------------------------------------------------
// Launch
// ---------------------------------------------------------------------------
extern "C" void kernel_launch(void* const* d_in, const int* in_sizes, int n_in,
                              void* d_out, int out_size) {
    (void)in_sizes; (void)n_in; (void)out_size;
    const float* x     = (const float*)d_in[0];
    const int*   wq    = (const int*)d_in[1];
    const float* scale = (const float*)d_in[2];
    const float* zp    = (const float*)d_in[3];
    const float* bias  = (const float*)d_in[4];
    float* out = (float*)d_out;

    cudaFuncSetAttribute(gemm_w2a16_kernel,
                         cudaFuncAttributeMaxDynamicSharedMemorySize, SMEM_BYTES);

    // fused prologue: 16384 blocks for x-convert + 8192 blocks for W-dequant
    prologue_kernel<<<24576, 256>>>(x, wq, scale, zp);

    dim3 grid(N_TOTAL / BN, M_TOTAL / BM);   // (16, 64) -> 1024 CTAs
    gemm_w2a16_kernel<<<grid, NTHREADS, SMEM_BYTES>>>(bias, out);
}

// round 14
// speedup vs baseline: 1.0112x; 1.0112x over previous
#include <cuda_runtime.h>
#include <cuda_fp16.h>
#include <cstdint>
#include <cstddef>

// Problem constants (fixed by the dataset)
static constexpr int M_TOTAL = 8192;   // B*S = 4*2048
static constexpr int N_TOTAL = 4096;
static constexpr int K_TOTAL = 4096;
static constexpr int GROUPS  = 64;     // K / 64

// GEMM tiling: CTA 128x256, 8 warps as 2(m) x 4(n), warp tile 64x64
static constexpr int BM = 128;
static constexpr int BN = 256;
static constexpr int BK = 64;                 // 64 fp16 = 128B per row
static constexpr int STAGES = 4;
static constexpr int KITERS = K_TOTAL / BK;   // 64
static constexpr int NTHREADS = 256;

static constexpr int A_STAGE_BYTES = BM * BK * 2;   // 16384
static constexpr int B_STAGE_BYTES = BN * BK * 2;   // 32768
static constexpr int STAGE_BYTES   = A_STAGE_BYTES + B_STAGE_BYTES; // 49152
static constexpr int DATA_OFF      = 1024;
static constexpr int SMEM_BYTES    = DATA_OFF + STAGES * STAGE_BYTES; // 197632

// fp16 scratch (device globals: the sanctioned scratch path)
__device__ __half g_Ah[(size_t)M_TOTAL * K_TOTAL];   // 64 MB
__device__ __half g_Bh[(size_t)N_TOTAL * K_TOTAL];   // 32 MB

// ---------------------------------------------------------------------------
// PTX helpers (baseline sm_80+ PTX — legal at target sm_103)
// ---------------------------------------------------------------------------
__device__ __forceinline__ uint32_t smem_u32(const void* p) {
    uint32_t a;
    asm("{ .reg .u64 t; cvta.to.shared.u64 t, %1; cvt.u32.u64 %0, t; }"
        : "=r"(a) : "l"(p));
    return a;
}

__device__ __forceinline__ void cp_async16(uint32_t dst, const void* src) {
    asm volatile("cp.async.cg.shared.global [%0], [%1], 16;"
                 :: "r"(dst), "l"(src) : "memory");
}

__device__ __forceinline__ void mbar_init(uint32_t addr, uint32_t count) {
    asm volatile("mbarrier.init.shared.b64 [%0], %1;"
                 :: "r"(addr), "r"(count) : "memory");
}

__device__ __forceinline__ void mbar_wait(uint32_t addr, uint32_t parity) {
    asm volatile(
        "{\n\t"
        ".reg .pred P;\n\t"
        "WL_%=:\n\t"
        "mbarrier.try_wait.parity.acquire.cta.shared::cta.b64 P, [%0], %1, 0x989680;\n\t"
        "@!P bra WL_%=;\n\t"
        "}"
        :: "r"(addr), "r"(parity) : "memory");
}

// Relaxed wait: ONLY for producer waits whose post-wait SMEM accesses are
// all async-proxy (cp.async) — ordered by their own completion mechanism.
__device__ __forceinline__ void mbar_wait_relaxed(uint32_t addr, uint32_t parity) {
    asm volatile(
        "{\n\t"
        ".reg .pred P;\n\t"
        "WL_%=:\n\t"
        "mbarrier.try_wait.parity.relaxed.cta.shared::cta.b64 P, [%0], %1, 0x989680;\n\t"
        "@!P bra WL_%=;\n\t"
        "}"
        :: "r"(addr), "r"(parity) : "memory");
}

__device__ __forceinline__ void mbar_arrive(uint32_t addr) {
    asm volatile("mbarrier.arrive.shared.b64 _, [%0];" :: "r"(addr) : "memory");
}

__device__ __forceinline__ void cp_async_arrive(uint32_t addr) {
    asm volatile("cp.async.mbarrier.arrive.noinc.shared.b64 [%0];"
                 :: "r"(addr) : "memory");
}

__device__ __forceinline__ void ldsm4(uint32_t* r, uint32_t addr) {
    asm volatile("ldmatrix.sync.aligned.m8n8.x4.shared.b16 {%0,%1,%2,%3}, [%4];"
                 : "=r"(r[0]), "=r"(r[1]), "=r"(r[2]), "=r"(r[3]) : "r"(addr));
}

__device__ __forceinline__ void mma16816(float* c, const uint32_t* a,
                                         const uint32_t* b) {
    asm volatile(
        "mma.sync.aligned.m16n8k16.row.col.f32.f16.f16.f32 "
        "{%0,%1,%2,%3}, {%4,%5,%6,%7}, {%8,%9}, {%0,%1,%2,%3};"
        : "+f"(c[0]), "+f"(c[1]), "+f"(c[2]), "+f"(c[3])
        : "r"(a[0]), "r"(a[1]), "r"(a[2]), "r"(a[3]), "r"(b[0]), "r"(b[1]));
}

// ---------------------------------------------------------------------------
// Fused prologue: fp32 x -> fp16 scratch (16 elems/thread), W -> fp16
// ---------------------------------------------------------------------------
__global__ void prologue_kernel(const float* __restrict__ x,
                                const int* __restrict__ wq,
                                const float* __restrict__ scale,
                                const float* __restrict__ zp) {
    if (blockIdx.x < 8192) {
        size_t i = ((size_t)blockIdx.x * blockDim.x + threadIdx.x) * 16;
        #pragma unroll
        for (int h = 0; h < 2; h++) {
            float4 a = *reinterpret_cast<const float4*>(x + i + h * 8);
            float4 b = *reinterpret_cast<const float4*>(x + i + h * 8 + 4);
            __half2 h0 = __floats2half2_rn(a.x, a.y);
            __half2 h1 = __floats2half2_rn(a.z, a.w);
            __half2 h2 = __floats2half2_rn(b.x, b.y);
            __half2 h3 = __floats2half2_rn(b.z, b.w);
            uint4 p;
            p.x = *reinterpret_cast<uint32_t*>(&h0);
            p.y = *reinterpret_cast<uint32_t*>(&h1);
            p.z = *reinterpret_cast<uint32_t*>(&h2);
            p.w = *reinterpret_cast<uint32_t*>(&h3);
            *reinterpret_cast<uint4*>(g_Ah + i + h * 8) = p;
        }
    } else {
        uint32_t c = (blockIdx.x - 8192) * blockDim.x + threadIdx.x;
        uint32_t n  = c >> 9;          // 512 chunks per row (K=4096)
        uint32_t kc = c & 511;
        uint32_t g  = kc >> 3;         // 8 chunks per 64-element group
        float s = __ldg(scale + (size_t)n * GROUPS + g);
        float z = __ldg(zp    + (size_t)n * GROUPS + g);
        const int4* qp =
            reinterpret_cast<const int4*>(wq + ((size_t)n << 12) + kc * 8);
        int4 q0 = qp[0];
        int4 q1 = qp[1];
        __half2 h0 = __floats2half2_rn(((float)q0.x - z) * s, ((float)q0.y - z) * s);
        __half2 h1 = __floats2half2_rn(((float)q0.z - z) * s, ((float)q0.w - z) * s);
        __half2 h2 = __floats2half2_rn(((float)q1.x - z) * s, ((float)q1.y - z) * s);
        __half2 h3 = __floats2half2_rn(((float)q1.z - z) * s, ((float)q1.w - z) * s);
        uint4 p;
        p.x = *reinterpret_cast<uint32_t*>(&h0);
        p.y = *reinterpret_cast<uint32_t*>(&h1);
        p.z = *reinterpret_cast<uint32_t*>(&h2);
        p.w = *reinterpret_cast<uint32_t*>(&h3);
        *reinterpret_cast<uint4*>(g_Bh + ((size_t)n << 12) + kc * 8) = p;
    }
}

// ---------------------------------------------------------------------------
// GEMM: out[M,N] = Ah[M,K] * Bh[N,K]^T + bias, fp16 mma.sync, fp32 accum
// 8 warps (2m x 4n), mbarrier ring, continuous cross-kt fragment pipeline.
// Producer issue after kk=0's MMA block (R11 structure, 564.8us), with the
// producer's EMPTY wait relaxed (post-wait accesses are async-proxy only).
// ---------------------------------------------------------------------------
__global__ void __launch_bounds__(NTHREADS, 1)
gemm_w2a16_kernel(const float* __restrict__ bias, float* __restrict__ out) {
    extern __shared__ char smem[];
    const uint32_t sb    = smem_u32(smem);
    const uint32_t FULL  = sb;        // 4 x 8B
    const uint32_t EMPTY = sb + 32;   // 4 x 8B
    const uint32_t DATA  = sb + DATA_OFF;

    const int tid  = threadIdx.x;
    const int lane = tid & 31;
    const int wid  = tid >> 5;
    const int wm   = wid & 1;     // 2 warps over M (64 rows each)
    const int wn   = wid >> 1;    // 4 warps over N (64 cols each)

    const int m0 = blockIdx.y * BM;
    const int n0 = blockIdx.x * BN;

    if (tid == 0) {
        #pragma unroll
        for (int s = 0; s < STAGES; s++) {
            mbar_init(FULL  + 8 * s, NTHREADS);
            mbar_init(EMPTY + 8 * s, NTHREADS);
        }
    }
    __syncthreads();

    // ---- per-thread producer addresses (hoisted; only +k0 varies) ----
    const int prow = tid >> 3, pcc = tid & 7;     // 32 rows per sweep
    const __half* asrc = g_Ah + (size_t)(m0 + prow) * K_TOTAL + pcc * 8;
    const __half* bsrc = g_Bh + (size_t)(n0 + prow) * K_TOTAL + pcc * 8;
    const uint32_t sw  = (uint32_t)((pcc ^ (prow & 7)) << 4);
    const uint32_t dA  = DATA + (uint32_t)prow * 128 + sw;
    const uint32_t dB  = DATA + A_STAGE_BYTES + (uint32_t)prow * 128 + sw;

    float acc[4][8][4];
    #pragma unroll
    for (int mi = 0; mi < 4; mi++)
        #pragma unroll
        for (int ni = 0; ni < 8; ni++)
            #pragma unroll
            for (int v = 0; v < 4; v++) acc[mi][ni][v] = 0.0f;

    // ---- prologue: issue stages 0..2 ----
    #pragma unroll
    for (int it = 0; it < STAGES - 1; it++) {
        const uint32_t st = it * STAGE_BYTES;
        const size_t   k0 = (size_t)it * BK;
        #pragma unroll
        for (int i = 0; i < 4; i++)   // A: 128 rows, 32 per sweep
            cp_async16(dA + st + i * 4096, asrc + (size_t)(i * 32) * K_TOTAL + k0);
        #pragma unroll
        for (int i = 0; i < 8; i++)   // B: 256 rows, 32 per sweep
            cp_async16(dB + st + i * 4096, bsrc + (size_t)(i * 32) * K_TOTAL + k0);
        cp_async_arrive(FULL + 8 * it);
    }

    // ---- per-thread ldmatrix address components ----
    const int quad = lane >> 3, lr = lane & 7;
    const uint32_t aByte = (uint32_t)((wm * 64 + (quad & 1) * 8 + lr) * 128);
    const int      aSel  = quad >> 1;
    const uint32_t bByte = (uint32_t)(A_STAGE_BYTES +
                           (wn * 64 + (quad >> 1) * 8 + lr) * 128);
    const int      bSel  = quad & 1;

    // double-buffered fragments
    uint32_t afr[2][4][4];
    uint32_t bfr[2][8][2];

    auto load_frags = [&](int buf, uint32_t st, int kk) {
        #pragma unroll
        for (int mi = 0; mi < 4; mi++)
            ldsm4(afr[buf][mi], st + aByte + mi * 2048 +
                  (((kk * 2 + aSel) ^ lr) << 4));
        #pragma unroll
        for (int nb = 0; nb < 4; nb++) {
            uint32_t r[4];
            ldsm4(r, st + bByte + nb * 2048 +
                  (((kk * 2 + bSel) ^ lr) << 4));
            bfr[buf][2 * nb][0]     = r[0]; bfr[buf][2 * nb][1]     = r[1];
            bfr[buf][2 * nb + 1][0] = r[2]; bfr[buf][2 * nb + 1][1] = r[3];
        }
    };

    // preamble: wait stage 0, load its kk=0 fragments into buffer 0
    mbar_wait(FULL, 0);
    load_frags(0, DATA, 0);

    for (int kt = 0; kt < KITERS; kt++) {
        const int cslot = kt & (STAGES - 1);
        const uint32_t st = DATA + cslot * STAGE_BYTES;

        #pragma unroll
        for (int kk = 0; kk < BK / 16; kk++) {
            const int cur = kk & 1, nxt = cur ^ 1;
            if (kk < BK / 16 - 1) {
                // prefetch kk+1 fragments of this stage
                load_frags(nxt, st, kk + 1);
            } else if (kt + 1 < KITERS) {
                // cross-kt: wait next stage, prefetch its kk=0, release this one
                const int nslot = (kt + 1) & (STAGES - 1);
                mbar_wait(FULL + 8 * nslot, ((kt + 1) >> 2) & 1);
                load_frags(nxt, DATA + nslot * STAGE_BYTES, 0);
                mbar_arrive(EMPTY + 8 * cslot);
            }
            #pragma unroll
            for (int mi = 0; mi < 4; mi++)
                #pragma unroll
                for (int ni = 0; ni < 8; ni++)
                    mma16816(acc[mi][ni], afr[cur][mi], bfr[cur][ni]);

            // ---- producer: issue stage kt+3 after kk=0's MMAs ----
            if (kk == 0) {
                const int it = kt + STAGES - 1;
                if (it < KITERS) {
                    const int islot = it & (STAGES - 1);
                    if (it >= STAGES)  // write-after-read (async-proxy only)
                        mbar_wait_relaxed(EMPTY + 8 * islot, ((it >> 2) - 1) & 1);
                    const uint32_t pst = islot * STAGE_BYTES;
                    const size_t   k0  = (size_t)it * BK;
                    #pragma unroll
                    for (int i = 0; i < 4; i++)
                        cp_async16(dA + pst + i * 4096,
                                   asrc + (size_t)(i * 32) * K_TOTAL + k0);
                    #pragma unroll
                    for (int i = 0; i < 8; i++)
                        cp_async16(dB + pst + i * 4096,
                                   bsrc + (size_t)(i * 32) * K_TOTAL + k0);
                    cp_async_arrive(FULL + 8 * islot);
                }
            }
        }
    }

    // epilogue: bias add + fp32 store (float2 per fragment row)
    const int orow = m0 + wm * 64 + (lane >> 2);
    const int ocol = n0 + wn * 64 + 2 * (lane & 3);
    #pragma unroll
    for (int ni = 0; ni < 8; ni++) {
        const float bx = __ldg(bias + ocol + ni * 8);
        const float by = __ldg(bias + ocol + ni * 8 + 1);
        #pragma unroll
        for (int mi = 0; mi < 4; mi++) {
            float2 v0 = make_float2(acc[mi][ni][0] + bx, acc[mi][ni][1] + by);
            float2 v1 = make_float2(acc[mi][ni][2] + bx, acc[mi][ni][3] + by);
            *reinterpret_cast<float2*>(
                out + (size_t)(orow + mi * 16) * N_TOTAL + ocol + ni * 8) = v0;
            *reinterpret_cast<float2*>(
                out + (size_t)(orow + mi * 16 + 8) * N_TOTAL + ocol + ni * 8) = v1;
        }
    }
}

// ---------------------------------------------------------------------------
// Launch
// ---------------------------------------------------------------------------
extern "C" void kernel_launch(void* const* d_in, const int* in_sizes, int n_in,
                              void* d_out, int out_size) {
    (void)in_sizes; (void)n_in; (void)out_size;
    const float* x     = (const float*)d_in[0];
    const int*   wq    = (const int*)d_in[1];
    const float* scale = (const float*)d_in[2];
    const float* zp    = (const float*)d_in[3];
    const float* bias  = (const float*)d_in[4];
    float* out = (float*)d_out;

    cudaFuncSetAttribute(gemm_w2a16_kernel,
                         cudaFuncAttributeMaxDynamicSharedMemorySize, SMEM_BYTES);

    // fused prologue: 8192 blocks for x-convert (16/thread) + 8192 for W-dequant
    prologue_kernel<<<16384, 256>>>(x, wq, scale, zp);

    dim3 grid(N_TOTAL / BN, M_TOTAL / BM);   // (16, 64) -> 1024 CTAs
    gemm_w2a16_kernel<<<grid, NTHREADS, SMEM_BYTES>>>(bias, out);
}

// round 15
// speedup vs baseline: 1.0295x; 1.0181x over previous
#include <cuda_runtime.h>
#include <cuda_fp16.h>
#include <cstdint>
#include <cstddef>

// Problem constants (fixed by the dataset)
static constexpr int M_TOTAL = 8192;   // B*S = 4*2048
static constexpr int N_TOTAL = 4096;
static constexpr int K_TOTAL = 4096;
static constexpr int GROUPS  = 64;     // K / 64

// GEMM tiling: CTA 128x256, 8 warps as 2(m) x 4(n), warp tile 64x64
static constexpr int BM = 128;
static constexpr int BN = 256;
static constexpr int BK = 64;                 // 64 fp16 = 128B per row
static constexpr int STAGES = 4;
static constexpr int KITERS = K_TOTAL / BK;   // 64
static constexpr int NTHREADS = 256;

static constexpr int A_STAGE_BYTES = BM * BK * 2;   // 16384
static constexpr int B_STAGE_BYTES = BN * BK * 2;   // 32768
static constexpr int STAGE_BYTES   = A_STAGE_BYTES + B_STAGE_BYTES; // 49152
static constexpr int DATA_OFF      = 1024;
static constexpr int SMEM_BYTES    = DATA_OFF + STAGES * STAGE_BYTES; // 197632

// fp16 scratch (device globals: the sanctioned scratch path)
__device__ __half g_Ah[(size_t)M_TOTAL * K_TOTAL];   // 64 MB
__device__ __half g_Bh[(size_t)N_TOTAL * K_TOTAL];   // 32 MB

// ---------------------------------------------------------------------------
// PTX helpers (baseline sm_80+ PTX — legal at target sm_103)
// ---------------------------------------------------------------------------
__device__ __forceinline__ uint32_t smem_u32(const void* p) {
    uint32_t a;
    asm("{ .reg .u64 t; cvta.to.shared.u64 t, %1; cvt.u32.u64 %0, t; }"
        : "=r"(a) : "l"(p));
    return a;
}

__device__ __forceinline__ void cp_async16(uint32_t dst, const void* src) {
    asm volatile("cp.async.cg.shared.global [%0], [%1], 16;"
                 :: "r"(dst), "l"(src) : "memory");
}

__device__ __forceinline__ void mbar_init(uint32_t addr, uint32_t count) {
    asm volatile("mbarrier.init.shared.b64 [%0], %1;"
                 :: "r"(addr), "r"(count) : "memory");
}

__device__ __forceinline__ void mbar_wait(uint32_t addr, uint32_t parity) {
    asm volatile(
        "{\n\t"
        ".reg .pred P;\n\t"
        "WL_%=:\n\t"
        "mbarrier.try_wait.parity.acquire.cta.shared::cta.b64 P, [%0], %1, 0x989680;\n\t"
        "@!P bra WL_%=;\n\t"
        "}"
        :: "r"(addr), "r"(parity) : "memory");
}

// Relaxed wait: ONLY for producer waits whose post-wait SMEM accesses are
// all async-proxy (cp.async) — ordered by their own completion mechanism.
__device__ __forceinline__ void mbar_wait_relaxed(uint32_t addr, uint32_t parity) {
    asm volatile(
        "{\n\t"
        ".reg .pred P;\n\t"
        "WL_%=:\n\t"
        "mbarrier.try_wait.parity.relaxed.cta.shared::cta.b64 P, [%0], %1, 0x989680;\n\t"
        "@!P bra WL_%=;\n\t"
        "}"
        :: "r"(addr), "r"(parity) : "memory");
}

__device__ __forceinline__ void mbar_arrive(uint32_t addr) {
    asm volatile("mbarrier.arrive.shared.b64 _, [%0];" :: "r"(addr) : "memory");
}

__device__ __forceinline__ void cp_async_arrive(uint32_t addr) {
    asm volatile("cp.async.mbarrier.arrive.noinc.shared.b64 [%0];"
                 :: "r"(addr) : "memory");
}

__device__ __forceinline__ void ldsm4(uint32_t* r, uint32_t addr) {
    asm volatile("ldmatrix.sync.aligned.m8n8.x4.shared.b16 {%0,%1,%2,%3}, [%4];"
                 : "=r"(r[0]), "=r"(r[1]), "=r"(r[2]), "=r"(r[3]) : "r"(addr));
}

__device__ __forceinline__ void mma16816(float* c, const uint32_t* a,
                                         const uint32_t* b) {
    asm volatile(
        "mma.sync.aligned.m16n8k16.row.col.f32.f16.f16.f32 "
        "{%0,%1,%2,%3}, {%4,%5,%6,%7}, {%8,%9}, {%0,%1,%2,%3};"
        : "+f"(c[0]), "+f"(c[1]), "+f"(c[2]), "+f"(c[3])
        : "r"(a[0]), "r"(a[1]), "r"(a[2]), "r"(a[3]), "r"(b[0]), "r"(b[1]));
}

// ---------------------------------------------------------------------------
// Fused prologue: fp32 x -> fp16 scratch (16 elems/thread), W -> fp16
// ---------------------------------------------------------------------------
__global__ void prologue_kernel(const float* __restrict__ x,
                                const int* __restrict__ wq,
                                const float* __restrict__ scale,
                                const float* __restrict__ zp) {
    if (blockIdx.x < 8192) {
        size_t i = ((size_t)blockIdx.x * blockDim.x + threadIdx.x) * 16;
        #pragma unroll
        for (int h = 0; h < 2; h++) {
            float4 a = *reinterpret_cast<const float4*>(x + i + h * 8);
            float4 b = *reinterpret_cast<const float4*>(x + i + h * 8 + 4);
            __half2 h0 = __floats2half2_rn(a.x, a.y);
            __half2 h1 = __floats2half2_rn(a.z, a.w);
            __half2 h2 = __floats2half2_rn(b.x, b.y);
            __half2 h3 = __floats2half2_rn(b.z, b.w);
            uint4 p;
            p.x = *reinterpret_cast<uint32_t*>(&h0);
            p.y = *reinterpret_cast<uint32_t*>(&h1);
            p.z = *reinterpret_cast<uint32_t*>(&h2);
            p.w = *reinterpret_cast<uint32_t*>(&h3);
            *reinterpret_cast<uint4*>(g_Ah + i + h * 8) = p;
        }
    } else {
        uint32_t c = (blockIdx.x - 8192) * blockDim.x + threadIdx.x;
        uint32_t n  = c >> 9;          // 512 chunks per row (K=4096)
        uint32_t kc = c & 511;
        uint32_t g  = kc >> 3;         // 8 chunks per 64-element group
        float s = __ldg(scale + (size_t)n * GROUPS + g);
        float z = __ldg(zp    + (size_t)n * GROUPS + g);
        const int4* qp =
            reinterpret_cast<const int4*>(wq + ((size_t)n << 12) + kc * 8);
        int4 q0 = qp[0];
        int4 q1 = qp[1];
        __half2 h0 = __floats2half2_rn(((float)q0.x - z) * s, ((float)q0.y - z) * s);
        __half2 h1 = __floats2half2_rn(((float)q0.z - z) * s, ((float)q0.w - z) * s);
        __half2 h2 = __floats2half2_rn(((float)q1.x - z) * s, ((float)q1.y - z) * s);
        __half2 h3 = __floats2half2_rn(((float)q1.z - z) * s, ((float)q1.w - z) * s);
        uint4 p;
        p.x = *reinterpret_cast<uint32_t*>(&h0);
        p.y = *reinterpret_cast<uint32_t*>(&h1);
        p.z = *reinterpret_cast<uint32_t*>(&h2);
        p.w = *reinterpret_cast<uint32_t*>(&h3);
        *reinterpret_cast<uint4*>(g_Bh + ((size_t)n << 12) + kc * 8) = p;
    }
}

// ---------------------------------------------------------------------------
// GEMM: out[M,N] = Ah[M,K] * Bh[N,K]^T + bias, fp16 mma.sync, fp32 accum
// 8 warps (2m x 4n), mbarrier ring, continuous cross-kt fragment pipeline.
// kt loop unrolled x4: ring-slot arithmetic and stage addresses constant-fold.
// ---------------------------------------------------------------------------
__global__ void __launch_bounds__(NTHREADS, 1)
gemm_w2a16_kernel(const float* __restrict__ bias, float* __restrict__ out) {
    extern __shared__ char smem[];
    const uint32_t sb    = smem_u32(smem);
    const uint32_t FULL  = sb;        // 4 x 8B
    const uint32_t EMPTY = sb + 32;   // 4 x 8B
    const uint32_t DATA  = sb + DATA_OFF;

    const int tid  = threadIdx.x;
    const int lane = tid & 31;
    const int wid  = tid >> 5;
    const int wm   = wid & 1;     // 2 warps over M (64 rows each)
    const int wn   = wid >> 1;    // 4 warps over N (64 cols each)

    const int m0 = blockIdx.y * BM;
    const int n0 = blockIdx.x * BN;

    if (tid == 0) {
        #pragma unroll
        for (int s = 0; s < STAGES; s++) {
            mbar_init(FULL  + 8 * s, NTHREADS);
            mbar_init(EMPTY + 8 * s, NTHREADS);
        }
    }
    __syncthreads();

    // ---- per-thread producer addresses (hoisted; only +k0 varies) ----
    const int prow = tid >> 3, pcc = tid & 7;     // 32 rows per sweep
    const __half* asrc = g_Ah + (size_t)(m0 + prow) * K_TOTAL + pcc * 8;
    const __half* bsrc = g_Bh + (size_t)(n0 + prow) * K_TOTAL + pcc * 8;
    const uint32_t sw  = (uint32_t)((pcc ^ (prow & 7)) << 4);
    const uint32_t dA  = DATA + (uint32_t)prow * 128 + sw;
    const uint32_t dB  = DATA + A_STAGE_BYTES + (uint32_t)prow * 128 + sw;

    float acc[4][8][4];
    #pragma unroll
    for (int mi = 0; mi < 4; mi++)
        #pragma unroll
        for (int ni = 0; ni < 8; ni++)
            #pragma unroll
            for (int v = 0; v < 4; v++) acc[mi][ni][v] = 0.0f;

    // ---- prologue: issue stages 0..2 ----
    #pragma unroll
    for (int it = 0; it < STAGES - 1; it++) {
        const uint32_t st = it * STAGE_BYTES;
        const size_t   k0 = (size_t)it * BK;
        #pragma unroll
        for (int i = 0; i < 4; i++)   // A: 128 rows, 32 per sweep
            cp_async16(dA + st + i * 4096, asrc + (size_t)(i * 32) * K_TOTAL + k0);
        #pragma unroll
        for (int i = 0; i < 8; i++)   // B: 256 rows, 32 per sweep
            cp_async16(dB + st + i * 4096, bsrc + (size_t)(i * 32) * K_TOTAL + k0);
        cp_async_arrive(FULL + 8 * it);
    }

    // ---- per-thread ldmatrix address components ----
    const int quad = lane >> 3, lr = lane & 7;
    const uint32_t aByte = (uint32_t)((wm * 64 + (quad & 1) * 8 + lr) * 128);
    const int      aSel  = quad >> 1;
    const uint32_t bByte = (uint32_t)(A_STAGE_BYTES +
                           (wn * 64 + (quad >> 1) * 8 + lr) * 128);
    const int      bSel  = quad & 1;

    // double-buffered fragments
    uint32_t afr[2][4][4];
    uint32_t bfr[2][8][2];

    auto load_frags = [&](int buf, uint32_t st, int kk) {
        #pragma unroll
        for (int mi = 0; mi < 4; mi++)
            ldsm4(afr[buf][mi], st + aByte + mi * 2048 +
                  (((kk * 2 + aSel) ^ lr) << 4));
        #pragma unroll
        for (int nb = 0; nb < 4; nb++) {
            uint32_t r[4];
            ldsm4(r, st + bByte + nb * 2048 +
                  (((kk * 2 + bSel) ^ lr) << 4));
            bfr[buf][2 * nb][0]     = r[0]; bfr[buf][2 * nb][1]     = r[1];
            bfr[buf][2 * nb + 1][0] = r[2]; bfr[buf][2 * nb + 1][1] = r[3];
        }
    };

    // preamble: wait stage 0, load its kk=0 fragments into buffer 0
    mbar_wait(FULL, 0);
    load_frags(0, DATA, 0);

    #pragma unroll 4
    for (int kt = 0; kt < KITERS; kt++) {
        const int cslot = kt & (STAGES - 1);
        const uint32_t st = DATA + cslot * STAGE_BYTES;

        #pragma unroll
        for (int kk = 0; kk < BK / 16; kk++) {
            const int cur = kk & 1, nxt = cur ^ 1;
            if (kk < BK / 16 - 1) {
                // prefetch kk+1 fragments of this stage
                load_frags(nxt, st, kk + 1);
            } else if (kt + 1 < KITERS) {
                // cross-kt: wait next stage, prefetch its kk=0, release this one
                const int nslot = (kt + 1) & (STAGES - 1);
                mbar_wait(FULL + 8 * nslot, ((kt + 1) >> 2) & 1);
                load_frags(nxt, DATA + nslot * STAGE_BYTES, 0);
                mbar_arrive(EMPTY + 8 * cslot);
            }
            #pragma unroll
            for (int mi = 0; mi < 4; mi++)
                #pragma unroll
                for (int ni = 0; ni < 8; ni++)
                    mma16816(acc[mi][ni], afr[cur][mi], bfr[cur][ni]);

            // ---- producer: issue stage kt+3 after kk=0's MMAs ----
            if (kk == 0) {
                const int it = kt + STAGES - 1;
                if (it < KITERS) {
                    const int islot = it & (STAGES - 1);
                    if (it >= STAGES)  // write-after-read (async-proxy only)
                        mbar_wait_relaxed(EMPTY + 8 * islot, ((it >> 2) - 1) & 1);
                    const uint32_t pst = islot * STAGE_BYTES;
                    const size_t   k0  = (size_t)it * BK;
                    #pragma unroll
                    for (int i = 0; i < 4; i++)
                        cp_async16(dA + pst + i * 4096,
                                   asrc + (size_t)(i * 32) * K_TOTAL + k0);
                    #pragma unroll
                    for (int i = 0; i < 8; i++)
                        cp_async16(dB + pst + i * 4096,
                                   bsrc + (size_t)(i * 32) * K_TOTAL + k0);
                    cp_async_arrive(FULL + 8 * islot);
                }
            }
        }
    }

    // epilogue: bias add + fp32 store (float2 per fragment row)
    const int orow = m0 + wm * 64 + (lane >> 2);
    const int ocol = n0 + wn * 64 + 2 * (lane & 3);
    #pragma unroll
    for (int ni = 0; ni < 8; ni++) {
        const float bx = __ldg(bias + ocol + ni * 8);
        const float by = __ldg(bias + ocol + ni * 8 + 1);
        #pragma unroll
        for (int mi = 0; mi < 4; mi++) {
            float2 v0 = make_float2(acc[mi][ni][0] + bx, acc[mi][ni][1] + by);
            float2 v1 = make_float2(acc[mi][ni][2] + bx, acc[mi][ni][3] + by);
            *reinterpret_cast<float2*>(
                out + (size_t)(orow + mi * 16) * N_TOTAL + ocol + ni * 8) = v0;
            *reinterpret_cast<float2*>(
                out + (size_t)(orow + mi * 16 + 8) * N_TOTAL + ocol + ni * 8) = v1;
        }
    }
}

// ---------------------------------------------------------------------------
// Launch
// ---------------------------------------------------------------------------
extern "C" void kernel_launch(void* const* d_in, const int* in_sizes, int n_in,
                              void* d_out, int out_size) {
    (void)in_sizes; (void)n_in; (void)out_size;
    const float* x     = (const float*)d_in[0];
    const int*   wq    = (const int*)d_in[1];
    const float* scale = (const float*)d_in[2];
    const float* zp    = (const float*)d_in[3];
    const float* bias  = (const float*)d_in[4];
    float* out = (float*)d_out;

    cudaFuncSetAttribute(gemm_w2a16_kernel,
                         cudaFuncAttributeMaxDynamicSharedMemorySize, SMEM_BYTES);

    // fused prologue: 8192 blocks for x-convert (16/thread) + 8192 for W-dequant
    prologue_kernel<<<16384, 256>>>(x, wq, scale, zp);

    dim3 grid(N_TOTAL / BN, M_TOTAL / BM);   // (16, 64) -> 1024 CTAs
    gemm_w2a16_kernel<<<grid, NTHREADS, SMEM_BYTES>>>(bias, out);
}

// round 16
// speedup vs baseline: 1.0337x; 1.0041x over previous
#include <cuda_runtime.h>
#include <cuda_fp16.h>
#include <cstdint>
#include <cstddef>

// Problem constants (fixed by the dataset)
static constexpr int M_TOTAL = 8192;   // B*S = 4*2048
static constexpr int N_TOTAL = 4096;
static constexpr int K_TOTAL = 4096;
static constexpr int GROUPS  = 64;     // K / 64

// GEMM tiling: CTA 128x256, 8 warps as 2(m) x 4(n), warp tile 64x64
static constexpr int BM = 128;
static constexpr int BN = 256;
static constexpr int BK = 64;                 // 64 fp16 = 128B per row
static constexpr int STAGES = 4;
static constexpr int KITERS = K_TOTAL / BK;   // 64
static constexpr int NTHREADS = 256;
static constexpr int NTILES_X = N_TOTAL / BN; // 16
static constexpr int NTILES   = (M_TOTAL / BM) * NTILES_X;  // 1024

static constexpr int A_STAGE_BYTES = BM * BK * 2;   // 16384
static constexpr int B_STAGE_BYTES = BN * BK * 2;   // 32768
static constexpr int STAGE_BYTES   = A_STAGE_BYTES + B_STAGE_BYTES; // 49152
static constexpr int DATA_OFF      = 1024;
static constexpr int SMEM_BYTES    = DATA_OFF + STAGES * STAGE_BYTES; // 197632

// fp16 scratch (device globals: the sanctioned scratch path)
__device__ __half g_Ah[(size_t)M_TOTAL * K_TOTAL];   // 64 MB
__device__ __half g_Bh[(size_t)N_TOTAL * K_TOTAL];   // 32 MB

// ---------------------------------------------------------------------------
// PTX helpers (baseline sm_80+ PTX — legal at target sm_103)
// ---------------------------------------------------------------------------
__device__ __forceinline__ uint32_t smem_u32(const void* p) {
    uint32_t a;
    asm("{ .reg .u64 t; cvta.to.shared.u64 t, %1; cvt.u32.u64 %0, t; }"
        : "=r"(a) : "l"(p));
    return a;
}

__device__ __forceinline__ void cp_async16(uint32_t dst, const void* src) {
    asm volatile("cp.async.cg.shared.global [%0], [%1], 16;"
                 :: "r"(dst), "l"(src) : "memory");
}

__device__ __forceinline__ void mbar_init(uint32_t addr, uint32_t count) {
    asm volatile("mbarrier.init.shared.b64 [%0], %1;"
                 :: "r"(addr), "r"(count) : "memory");
}

__device__ __forceinline__ void mbar_wait(uint32_t addr, uint32_t parity) {
    asm volatile(
        "{\n\t"
        ".reg .pred P;\n\t"
        "WL_%=:\n\t"
        "mbarrier.try_wait.parity.acquire.cta.shared::cta.b64 P, [%0], %1, 0x989680;\n\t"
        "@!P bra WL_%=;\n\t"
        "}"
        :: "r"(addr), "r"(parity) : "memory");
}

// Relaxed wait: ONLY for producer waits whose post-wait SMEM accesses are
// all async-proxy (cp.async) — ordered by their own completion mechanism.
__device__ __forceinline__ void mbar_wait_relaxed(uint32_t addr, uint32_t parity) {
    asm volatile(
        "{\n\t"
        ".reg .pred P;\n\t"
        "WL_%=:\n\t"
        "mbarrier.try_wait.parity.relaxed.cta.shared::cta.b64 P, [%0], %1, 0x989680;\n\t"
        "@!P bra WL_%=;\n\t"
        "}"
        :: "r"(addr), "r"(parity) : "memory");
}

__device__ __forceinline__ void mbar_arrive(uint32_t addr) {
    asm volatile("mbarrier.arrive.shared.b64 _, [%0];" :: "r"(addr) : "memory");
}

__device__ __forceinline__ void cp_async_arrive(uint32_t addr) {
    asm volatile("cp.async.mbarrier.arrive.noinc.shared.b64 [%0];"
                 :: "r"(addr) : "memory");
}

__device__ __forceinline__ void ldsm4(uint32_t* r, uint32_t addr) {
    asm volatile("ldmatrix.sync.aligned.m8n8.x4.shared.b16 {%0,%1,%2,%3}, [%4];"
                 : "=r"(r[0]), "=r"(r[1]), "=r"(r[2]), "=r"(r[3]) : "r"(addr));
}

__device__ __forceinline__ void mma16816(float* c, const uint32_t* a,
                                         const uint32_t* b) {
    asm volatile(
        "mma.sync.aligned.m16n8k16.row.col.f32.f16.f16.f32 "
        "{%0,%1,%2,%3}, {%4,%5,%6,%7}, {%8,%9}, {%0,%1,%2,%3};"
        : "+f"(c[0]), "+f"(c[1]), "+f"(c[2]), "+f"(c[3])
        : "r"(a[0]), "r"(a[1]), "r"(a[2]), "r"(a[3]), "r"(b[0]), "r"(b[1]));
}

// ---------------------------------------------------------------------------
// Fused prologue: fp32 x -> fp16 scratch (16 elems/thread), W -> fp16
// ---------------------------------------------------------------------------
__global__ void prologue_kernel(const float* __restrict__ x,
                                const int* __restrict__ wq,
                                const float* __restrict__ scale,
                                const float* __restrict__ zp) {
    if (blockIdx.x < 8192) {
        size_t i = ((size_t)blockIdx.x * blockDim.x + threadIdx.x) * 16;
        #pragma unroll
        for (int h = 0; h < 2; h++) {
            float4 a = *reinterpret_cast<const float4*>(x + i + h * 8);
            float4 b = *reinterpret_cast<const float4*>(x + i + h * 8 + 4);
            __half2 h0 = __floats2half2_rn(a.x, a.y);
            __half2 h1 = __floats2half2_rn(a.z, a.w);
            __half2 h2 = __floats2half2_rn(b.x, b.y);
            __half2 h3 = __floats2half2_rn(b.z, b.w);
            uint4 p;
            p.x = *reinterpret_cast<uint32_t*>(&h0);
            p.y = *reinterpret_cast<uint32_t*>(&h1);
            p.z = *reinterpret_cast<uint32_t*>(&h2);
            p.w = *reinterpret_cast<uint32_t*>(&h3);
            *reinterpret_cast<uint4*>(g_Ah + i + h * 8) = p;
        }
    } else {
        uint32_t c = (blockIdx.x - 8192) * blockDim.x + threadIdx.x;
        uint32_t n  = c >> 9;          // 512 chunks per row (K=4096)
        uint32_t kc = c & 511;
        uint32_t g  = kc >> 3;         // 8 chunks per 64-element group
        float s = __ldg(scale + (size_t)n * GROUPS + g);
        float z = __ldg(zp    + (size_t)n * GROUPS + g);
        const int4* qp =
            reinterpret_cast<const int4*>(wq + ((size_t)n << 12) + kc * 8);
        int4 q0 = qp[0];
        int4 q1 = qp[1];
        __half2 h0 = __floats2half2_rn(((float)q0.x - z) * s, ((float)q0.y - z) * s);
        __half2 h1 = __floats2half2_rn(((float)q0.z - z) * s, ((float)q0.w - z) * s);
        __half2 h2 = __floats2half2_rn(((float)q1.x - z) * s, ((float)q1.y - z) * s);
        __half2 h3 = __floats2half2_rn(((float)q1.z - z) * s, ((float)q1.w - z) * s);
        uint4 p;
        p.x = *reinterpret_cast<uint32_t*>(&h0);
        p.y = *reinterpret_cast<uint32_t*>(&h1);
        p.z = *reinterpret_cast<uint32_t*>(&h2);
        p.w = *reinterpret_cast<uint32_t*>(&h3);
        *reinterpret_cast<uint4*>(g_Bh + ((size_t)n << 12) + kc * 8) = p;
    }
}

// ---------------------------------------------------------------------------
// Persistent GEMM: tiles cta, cta+nsm, ... ; never-draining mbarrier ring.
// EMPTY barriers are "primed" once at init so the producer wait parity is the
// tile-invariant (it>>2)&1 — mainloop is byte-identical for every tile.
// Next tile's 3 pipeline stages are issued BEFORE this tile's epilogue, so
// the epilogue overlaps the fill.
// ---------------------------------------------------------------------------
__global__ void __launch_bounds__(NTHREADS, 1)
gemm_w2a16_kernel(const float* __restrict__ bias, float* __restrict__ out,
                  int nsm) {
    extern __shared__ char smem[];
    const uint32_t sb    = smem_u32(smem);
    const uint32_t FULL  = sb;        // 4 x 8B
    const uint32_t EMPTY = sb + 32;   // 4 x 8B
    const uint32_t DATA  = sb + DATA_OFF;

    const int tid  = threadIdx.x;
    const int lane = tid & 31;
    const int wid  = tid >> 5;
    const int wm   = wid & 1;     // 2 warps over M (64 rows each)
    const int wn   = wid >> 1;    // 4 warps over N (64 cols each)
    const int cta  = blockIdx.x;

    const int my_ntiles = (NTILES - 1 - cta) / nsm + 1;

    if (tid == 0) {
        #pragma unroll
        for (int s = 0; s < STAGES; s++) {
            mbar_init(FULL  + 8 * s, NTHREADS);
            mbar_init(EMPTY + 8 * s, NTHREADS);
        }
    }
    __syncthreads();

    // prime EMPTY: complete phase 0 on every slot (all threads arrive once)
    #pragma unroll
    for (int s = 0; s < STAGES; s++) mbar_arrive(EMPTY + 8 * s);

    // ---- per-thread producer sub-offsets (tile-independent) ----
    const int prow = tid >> 3, pcc = tid & 7;     // 32 rows per sweep
    const uint32_t sw  = (uint32_t)((pcc ^ (prow & 7)) << 4);
    const uint32_t dA  = DATA + (uint32_t)prow * 128 + sw;
    const uint32_t dB  = DATA + A_STAGE_BYTES + (uint32_t)prow * 128 + sw;

    // producer tile pointers (updated at tile boundaries, OUTSIDE mainloop)
    int tt = cta;
    const __half* asrc = g_Ah + (size_t)((tt >> 4) * BM + prow) * K_TOTAL + pcc * 8;
    const __half* bsrc = g_Bh + (size_t)((tt & (NTILES_X - 1)) * BN + prow) * K_TOTAL + pcc * 8;

    // ---- issue tile-0 stages 0..2 (EMPTY parity 0 = primed, passes) ----
    #pragma unroll
    for (int it = 0; it < STAGES - 1; it++) {
        mbar_wait_relaxed(EMPTY + 8 * it, 0);
        const uint32_t st = it * STAGE_BYTES;
        const size_t   k0 = (size_t)it * BK;
        #pragma unroll
        for (int i = 0; i < 4; i++)
            cp_async16(dA + st + i * 4096, asrc + (size_t)(i * 32) * K_TOTAL + k0);
        #pragma unroll
        for (int i = 0; i < 8; i++)
            cp_async16(dB + st + i * 4096, bsrc + (size_t)(i * 32) * K_TOTAL + k0);
        cp_async_arrive(FULL + 8 * it);
    }

    // ---- per-thread ldmatrix address components ----
    const int quad = lane >> 3, lr = lane & 7;
    const uint32_t aByte = (uint32_t)((wm * 64 + (quad & 1) * 8 + lr) * 128);
    const int      aSel  = quad >> 1;
    const uint32_t bByte = (uint32_t)(A_STAGE_BYTES +
                           (wn * 64 + (quad >> 1) * 8 + lr) * 128);
    const int      bSel  = quad & 1;

    // double-buffered fragments
    uint32_t afr[2][4][4];
    uint32_t bfr[2][8][2];

    auto load_frags = [&](int buf, uint32_t st, int kk) {
        #pragma unroll
        for (int mi = 0; mi < 4; mi++)
            ldsm4(afr[buf][mi], st + aByte + mi * 2048 +
                  (((kk * 2 + aSel) ^ lr) << 4));
        #pragma unroll
        for (int nb = 0; nb < 4; nb++) {
            uint32_t r[4];
            ldsm4(r, st + bByte + nb * 2048 +
                  (((kk * 2 + bSel) ^ lr) << 4));
            bfr[buf][2 * nb][0]     = r[0]; bfr[buf][2 * nb][1]     = r[1];
            bfr[buf][2 * nb + 1][0] = r[2]; bfr[buf][2 * nb + 1][1] = r[3];
        }
    };

    for (int j = 0; j < my_ntiles; j++) {
        float acc[4][8][4];
        #pragma unroll
        for (int mi = 0; mi < 4; mi++)
            #pragma unroll
            for (int ni = 0; ni < 8; ni++)
                #pragma unroll
                for (int v = 0; v < 4; v++) acc[mi][ni][v] = 0.0f;

        // preamble: wait stage 0 (parity 0, tile-invariant), load kk=0 frags
        mbar_wait(FULL, 0);
        load_frags(0, DATA, 0);

        #pragma unroll 4
        for (int kt = 0; kt < KITERS; kt++) {
            const int cslot = kt & (STAGES - 1);
            const uint32_t st = DATA + cslot * STAGE_BYTES;

            #pragma unroll
            for (int kk = 0; kk < BK / 16; kk++) {
                const int cur = kk & 1, nxt = cur ^ 1;
                if (kk < BK / 16 - 1) {
                    load_frags(nxt, st, kk + 1);
                } else if (kt + 1 < KITERS) {
                    const int nslot = (kt + 1) & (STAGES - 1);
                    mbar_wait(FULL + 8 * nslot, ((kt + 1) >> 2) & 1);
                    load_frags(nxt, DATA + nslot * STAGE_BYTES, 0);
                    mbar_arrive(EMPTY + 8 * cslot);
                }
                #pragma unroll
                for (int mi = 0; mi < 4; mi++)
                    #pragma unroll
                    for (int ni = 0; ni < 8; ni++)
                        mma16816(acc[mi][ni], afr[cur][mi], bfr[cur][ni]);

                // producer: issue stage kt+3 after kk=0's MMAs.
                // EMPTY wait parity (it>>2)&1 — valid for every tile thanks
                // to the primed phase-0 round (16 phases/slot/tile = even).
                if (kk == 0) {
                    const int it = kt + STAGES - 1;
                    if (it < KITERS) {
                        const int islot = it & (STAGES - 1);
                        mbar_wait_relaxed(EMPTY + 8 * islot, (it >> 2) & 1);
                        const uint32_t pst = islot * STAGE_BYTES;
                        const size_t   k0  = (size_t)it * BK;
                        #pragma unroll
                        for (int i = 0; i < 4; i++)
                            cp_async16(dA + pst + i * 4096,
                                       asrc + (size_t)(i * 32) * K_TOTAL + k0);
                        #pragma unroll
                        for (int i = 0; i < 8; i++)
                            cp_async16(dB + pst + i * 4096,
                                       bsrc + (size_t)(i * 32) * K_TOTAL + k0);
                        cp_async_arrive(FULL + 8 * islot);
                    }
                }
            }
        }

        // slot 3's release is skipped inside the mainloop at kt=63 — supply
        // it here so every slot completes exactly 16 phases per tile.
        mbar_arrive(EMPTY + 24);

        const int tt_out = tt;

        // ---- issue next tile's stages 0..2 BEFORE the epilogue ----
        if (j + 1 < my_ntiles) {
            tt += nsm;
            asrc = g_Ah + (size_t)((tt >> 4) * BM + prow) * K_TOTAL + pcc * 8;
            bsrc = g_Bh + (size_t)((tt & (NTILES_X - 1)) * BN + prow) * K_TOTAL + pcc * 8;
            #pragma unroll
            for (int it = 0; it < STAGES - 1; it++) {
                mbar_wait_relaxed(EMPTY + 8 * it, 0);
                const uint32_t st = it * STAGE_BYTES;
                const size_t   k0 = (size_t)it * BK;
                #pragma unroll
                for (int i = 0; i < 4; i++)
                    cp_async16(dA + st + i * 4096,
                               asrc + (size_t)(i * 32) * K_TOTAL + k0);
                #pragma unroll
                for (int i = 0; i < 8; i++)
                    cp_async16(dB + st + i * 4096,
                               bsrc + (size_t)(i * 32) * K_TOTAL + k0);
                cp_async_arrive(FULL + 8 * it);
            }
        }

        // ---- epilogue for tile tt_out (overlaps the fill above) ----
        {
            const int m0 = (tt_out >> 4) * BM;
            const int n0 = (tt_out & (NTILES_X - 1)) * BN;
            const int orow = m0 + wm * 64 + (lane >> 2);
            const int ocol = n0 + wn * 64 + 2 * (lane & 3);
            #pragma unroll
            for (int ni = 0; ni < 8; ni++) {
                const float bx = __ldg(bias + ocol + ni * 8);
                const float by = __ldg(bias + ocol + ni * 8 + 1);
                #pragma unroll
                for (int mi = 0; mi < 4; mi++) {
                    float2 v0 = make_float2(acc[mi][ni][0] + bx,
                                            acc[mi][ni][1] + by);
                    float2 v1 = make_float2(acc[mi][ni][2] + bx,
                                            acc[mi][ni][3] + by);
                    *reinterpret_cast<float2*>(
                        out + (size_t)(orow + mi * 16) * N_TOTAL + ocol + ni * 8) = v0;
                    *reinterpret_cast<float2*>(
                        out + (size_t)(orow + mi * 16 + 8) * N_TOTAL + ocol + ni * 8) = v1;
                }
            }
        }
    }
}

// ---------------------------------------------------------------------------
// Launch
// ---------------------------------------------------------------------------
extern "C" void kernel_launch(void* const* d_in, const int* in_sizes, int n_in,
                              void* d_out, int out_size) {
    (void)in_sizes; (void)n_in; (void)out_size;
    const float* x     = (const float*)d_in[0];
    const int*   wq    = (const int*)d_in[1];
    const float* scale = (const float*)d_in[2];
    const float* zp    = (const float*)d_in[3];
    const float* bias  = (const float*)d_in[4];
    float* out = (float*)d_out;

    static int nsm = 0;
    if (nsm == 0) {
        cudaDeviceGetAttribute(&nsm, cudaDevAttrMultiProcessorCount, 0);
        if (nsm <= 0) nsm = 148;
        cudaFuncSetAttribute(gemm_w2a16_kernel,
                             cudaFuncAttributeMaxDynamicSharedMemorySize,
                             SMEM_BYTES);
    }

    // fused prologue: 8192 blocks for x-convert (16/thread) + 8192 for W-dequant
    prologue_kernel<<<16384, 256>>>(x, wq, scale, zp);

    gemm_w2a16_kernel<<<nsm, NTHREADS, SMEM_BYTES>>>(bias, out, nsm);
}